// round 6
// baseline (speedup 1.0000x reference)
#include <cuda_runtime.h>
#include <cuda_bf16.h>
#include <math.h>
#include <stdint.h>

// ---------------------------------------------------------------------------
// HierarchicalAffinityLoss via bf16-split (hi/lo) mma.sync GEMM, round 5.
// 128x128 CTA tile, 32x64 warp tile: halves per-output SMEM/ldmatrix traffic
// (R4 was crossbar-bound at 490 MAC/cyc/SM). XOR-swizzled 512B rows, A panel
// resident in SMEM, B streamed in k64 chunks (2-stage cp.async pipeline).
// B = 8192, D = 256.
// ---------------------------------------------------------------------------

#define MAX_B 8192
#define MAX_D 256
#define MARGIN 0.3f

#define BMC 128                      // CTA rows
#define BNC 128                      // CTA tile cols
#define NSPLIT 8                     // column splits (grid.y)
#define NSPLIT_EFF 16                // NSPLIT * 2 warp_n groups
#define COLSPAN (MAX_B / NSPLIT)     // 1024
#define NT (COLSPAN / BNC)           // 8 tiles per CTA
#define NQ (NT * 4)                  // 32 k64-chunks per CTA

// SMEM layout (512B rows, XOR swizzle chunk^(row&7); no padding)
#define A_HI   0                     // 128 rows x 512B = 64KB
#define A_LO   65536                 // 64KB
#define B_BUF  131072                // 2 stages x 32KB
#define B_STAGE 32768
#define B_LOO  16384                 // lo half within a stage
#define SFAM   196608                // 1024 ints = 4KB
#define SM_TOTAL 200704

__device__ __nv_bfloat16 g_hi[MAX_B * MAX_D];
__device__ __nv_bfloat16 g_lo[MAX_B * MAX_D];
__device__ int   g_fam[MAX_B];
__device__ float g_pmin[NSPLIT_EFF * MAX_B];
__device__ float g_pmax[NSPLIT_EFF * MAX_B];

__device__ __constant__ int c_fam_table[6] = {0, 1, 2, 1, 3, 3};

// ======================= PTX helpers =======================================
__device__ __forceinline__ uint32_t smem_u32(const void* p) {
    uint32_t a;
    asm("{ .reg .u64 t; cvta.to.shared.u64 t, %1; cvt.u32.u64 %0, t; }"
        : "=r"(a) : "l"(p));
    return a;
}
#define CP_ASYNC16(saddr, gaddr) \
    asm volatile("cp.async.cg.shared.global [%0], [%1], 16;" :: "r"(saddr), "l"(gaddr))
#define CP_ASYNC_COMMIT() asm volatile("cp.async.commit_group;" ::: "memory")
#define CP_ASYNC_WAIT0()  asm volatile("cp.async.wait_group 0;" ::: "memory")
#define CP_ASYNC_WAIT1()  asm volatile("cp.async.wait_group 1;" ::: "memory")

#define LDSM_X4(r, addr)                                                    \
    asm volatile("ldmatrix.sync.aligned.m8n8.x4.shared.b16 {%0,%1,%2,%3}, [%4];" \
        : "=r"((r)[0]), "=r"((r)[1]), "=r"((r)[2]), "=r"((r)[3]) : "r"(addr))
#define MMA16816(d, a, b0, b1)                                              \
    asm volatile("mma.sync.aligned.m16n8k16.row.col.f32.bf16.bf16.f32 "     \
        "{%0,%1,%2,%3},{%4,%5,%6,%7},{%8,%9},{%0,%1,%2,%3};"                \
        : "+f"((d)[0]), "+f"((d)[1]), "+f"((d)[2]), "+f"((d)[3])            \
        : "r"((a)[0]), "r"((a)[1]), "r"((a)[2]), "r"((a)[3]),               \
          "r"(b0), "r"(b1))

// ---------------------------------------------------------------------------
// Kernel 1: row L2-normalize + split into bf16 hi/lo. One warp per row.
// ---------------------------------------------------------------------------
__global__ __launch_bounds__(256) void norm_split_kernel(const float* __restrict__ emb,
                                                         int B, int D) {
    int row = blockIdx.x * (blockDim.x >> 5) + (threadIdx.x >> 5);
    if (row >= B) return;
    int lane = threadIdx.x & 31;
    const float* src = emb + (size_t)row * D;
    float s = 0.f;
    for (int k = lane; k < D; k += 32) {
        float v = src[k];
        s = fmaf(v, v, s);
    }
    #pragma unroll
    for (int off = 16; off > 0; off >>= 1)
        s += __shfl_xor_sync(0xffffffffu, s, off);
    float inv = 1.0f / sqrtf(s);
    for (int k = lane; k < D; k += 32) {
        float v = src[k] * inv;
        __nv_bfloat16 h = __float2bfloat16(v);
        float lo = v - __bfloat162float(h);
        g_hi[(size_t)row * D + k] = h;
        g_lo[(size_t)row * D + k] = __float2bfloat16(lo);
    }
}

// ---------------------------------------------------------------------------
// Kernel 2: family lookup with int64/int32 auto-detect (proven in R2/R4).
// ---------------------------------------------------------------------------
__global__ void fam_kernel(const int* __restrict__ lab32, int B) {
    int t = threadIdx.x;
    int bad = 0;
    if (t < 64) {
        int lo = lab32[2 * t];
        int hi = lab32[2 * t + 1];
        if (hi != 0 || lo < 0 || lo >= 64) bad = 1;
    }
    int any_bad = __syncthreads_or(bad);
    bool as64 = (any_bad == 0);
    for (int i = t; i < B; i += blockDim.x) {
        long long l;
        if (as64) l = ((const long long*)lab32)[i];
        else      l = (long long)lab32[i];
        int fam;
        if (l < 6) {
            int idx = (int)l;
            if (idx < 0) idx = 0;
            if (idx > 5) idx = 5;
            fam = c_fam_table[idx];
        } else {
            fam = -1;
        }
        g_fam[i] = fam;
    }
}

// ---------------------------------------------------------------------------
// B k64-chunk loader: 128 cols x 64 k (hi+lo) = 32KB into one stage.
// Col j row = 128B = 8 x 16B chunks, swizzle c^(j&7).
// ---------------------------------------------------------------------------
__device__ __forceinline__ void load_b_chunk(uint32_t sb, int jc0, int q,
                                             int buf, int tid) {
    const int j0 = jc0 + (q >> 2) * BNC;
    const int kb = (q & 3) * 64;
    const uint32_t dst = sb + B_BUF + buf * B_STAGE;
    const char* ghi = (const char*)g_hi;
    const char* glo = (const char*)g_lo;
    #pragma unroll
    for (int it = 0; it < 4; it++) {
        int idx = it * 256 + tid;             // 0..1023
        int j = idx >> 3, c = idx & 7;
        uint32_t soff = (uint32_t)(j * 128 + ((c ^ (j & 7)) << 4));
        size_t goff = ((size_t)(j0 + j) * MAX_D + kb + c * 8) * 2;
        CP_ASYNC16(dst + soff, ghi + goff);
        CP_ASYNC16(dst + B_LOO + soff, glo + goff);
    }
}

// ---------------------------------------------------------------------------
// Kernel 3: bf16-split mma.sync Gram + fused masked min/max.
// ---------------------------------------------------------------------------
__global__ __launch_bounds__(256, 1) void sim_mma_kernel() {
    extern __shared__ char smem[];
    const uint32_t sb = smem_u32(smem);
    const int tid = threadIdx.x;
    const int wid = tid >> 5;
    const int lane = tid & 31;
    const int i0 = blockIdx.x * BMC;
    const int split = blockIdx.y;
    const int jc0 = split * COLSPAN;

    const int warp_m = wid & 3;          // 4 row-warps, 32 rows each
    const int warp_n = wid >> 2;         // 2 col-warps, 64 cols each
    const int m0 = warp_m * 32;

    // ---- prologue: resident A panel (hi+lo, swizzled 512B rows) ----
    {
        const char* ghi = (const char*)g_hi;
        const char* glo = (const char*)g_lo;
        #pragma unroll
        for (int it = 0; it < 16; it++) {
            int idx = it * 256 + tid;        // 0..4095
            int r = idx >> 5, c = idx & 31;
            uint32_t soff = (uint32_t)(r * 512 + ((c ^ (r & 7)) << 4));
            size_t goff = ((size_t)(i0 + r) * MAX_D + c * 8) * 2;
            CP_ASYNC16(sb + A_HI + soff, ghi + goff);
            CP_ASYNC16(sb + A_LO + soff, glo + goff);
        }
    }
    load_b_chunk(sb, jc0, 0, 0, tid);
    CP_ASYNC_COMMIT();                       // group0: A + chunk0
    load_b_chunk(sb, jc0, 1, 1, tid);
    CP_ASYNC_COMMIT();                       // group1: chunk1

    // fam cache for this CTA's column span
    int* sfam = (int*)(smem + SFAM);
    for (int c = tid; c < COLSPAN; c += 256)
        sfam[c] = g_fam[jc0 + c];

    // per-thread row state: 4 rows (2 m16-frags x 2 row-groups)
    const int g8 = lane >> 2;
    int rows[4], fam_i[4];
    float minS[4], maxD[4];
    #pragma unroll
    for (int r = 0; r < 4; r++) {
        rows[r] = i0 + m0 + r * 8 + g8;
        fam_i[r] = g_fam[rows[r]];
        minS[r] = 1e38f; maxD[r] = -1e38f;
    }

    // ldmatrix lane bases
    // A x4 serves rows ra..ra+15: lanes 0-7 row ra+l (k c), 8-15 row ra+8+l (k c),
    // 16-23 row ra+l (k c+1), 24-31 row ra+8+l (k c+1).
    const int arow = m0 + (lane & 7) + ((lane >> 3) & 1) * 8;  // first 16 rows
    const int sA = arow & 7;                                    // same for +16
    const uint32_t aHi0 = sb + A_HI + (uint32_t)(arow * 512);
    const uint32_t aHi1 = aHi0 + 16 * 512;
    const uint32_t aLo0 = sb + A_LO + (uint32_t)(arow * 512);
    const uint32_t aLo1 = aLo0 + 16 * 512;
    const int cLaneA = (lane >> 4);          // +1 chunk for upper half-warp

    // B x4 serves cols jb..jb+15 per np
    const int jbl = (lane & 7) + ((lane >> 3) & 1) * 8;

    CP_ASYNC_WAIT1();                        // A + chunk0 ready
    __syncthreads();

    float acc[2][8][4];
    #pragma unroll
    for (int mf = 0; mf < 2; mf++)
        #pragma unroll
        for (int nf = 0; nf < 8; nf++)
            #pragma unroll
            for (int c = 0; c < 4; c++) acc[mf][nf][c] = 0.f;

    for (int q = 0; q < NQ; q++) {
        const int buf = q & 1;
        const int kq = q & 3;
        const uint32_t bufb = sb + B_BUF + buf * B_STAGE;

        #pragma unroll
        for (int kk = 0; kk < 4; kk++) {
            const int cA = kq * 8 + 2 * kk + cLaneA;      // A chunk idx 0..31
            const uint32_t aoff = (uint32_t)((cA ^ sA) << 4);
            uint32_t ah0[4], ah1[4], al0[4], al1[4];
            LDSM_X4(ah0, aHi0 + aoff);
            LDSM_X4(ah1, aHi1 + aoff);
            LDSM_X4(al0, aLo0 + aoff);
            LDSM_X4(al1, aLo1 + aoff);

            #pragma unroll
            for (int np = 0; np < 4; np++) {
                const int j = warp_n * 64 + np * 16 + jbl;
                const int cB = 2 * kk + cLaneA;           // B chunk idx 0..7
                const uint32_t boff = (uint32_t)(j * 128 + ((cB ^ (j & 7)) << 4));
                uint32_t bh[4], bl[4];
                LDSM_X4(bh, bufb + boff);
                LDSM_X4(bl, bufb + B_LOO + boff);
                // frags: even n-tile = {r0,r2}, odd n-tile = {r1,r3}
                MMA16816(acc[0][2*np],   ah0, bh[0], bh[2]);
                MMA16816(acc[0][2*np+1], ah0, bh[1], bh[3]);
                MMA16816(acc[1][2*np],   ah1, bh[0], bh[2]);
                MMA16816(acc[1][2*np+1], ah1, bh[1], bh[3]);
                MMA16816(acc[0][2*np],   al0, bh[0], bh[2]);
                MMA16816(acc[0][2*np+1], al0, bh[1], bh[3]);
                MMA16816(acc[1][2*np],   al1, bh[0], bh[2]);
                MMA16816(acc[1][2*np+1], al1, bh[1], bh[3]);
                MMA16816(acc[0][2*np],   ah0, bl[0], bl[2]);
                MMA16816(acc[0][2*np+1], ah0, bl[1], bl[3]);
                MMA16816(acc[1][2*np],   ah1, bl[0], bl[2]);
                MMA16816(acc[1][2*np+1], ah1, bl[1], bl[3]);
            }
        }

        // tile complete -> masked min/max epilogue, reset acc
        if (kq == 3) {
            const int tjl = (q >> 2) * BNC + warp_n * 64;   // tile col base, local
            #pragma unroll
            for (int nf = 0; nf < 8; nf++) {
                const int jl = tjl + nf * 8 + (lane & 3) * 2;
                const int j0 = jc0 + jl;
                const int fj0 = sfam[jl];
                const int fj1 = sfam[jl + 1];
                #pragma unroll
                for (int mf = 0; mf < 2; mf++) {
                    #pragma unroll
                    for (int h = 0; h < 2; h++) {         // row-group within frag
                        const int ri = mf * 2 + h;
                        if (fam_i[ri] < 0) continue;
                        const float v0 = acc[mf][nf][h * 2];
                        const float v1 = acc[mf][nf][h * 2 + 1];
                        if (fj0 == fam_i[ri]) { if (j0 != rows[ri]) minS[ri] = fminf(minS[ri], v0); }
                        else if (fj0 >= 0) maxD[ri] = fmaxf(maxD[ri], v0);
                        if (fj1 == fam_i[ri]) { if (j0 + 1 != rows[ri]) minS[ri] = fminf(minS[ri], v1); }
                        else if (fj1 >= 0) maxD[ri] = fmaxf(maxD[ri], v1);
                    }
                }
            }
            #pragma unroll
            for (int mf = 0; mf < 2; mf++)
                #pragma unroll
                for (int nf = 0; nf < 8; nf++)
                    #pragma unroll
                    for (int c = 0; c < 4; c++) acc[mf][nf][c] = 0.f;
        }

        __syncthreads();                      // all warps done with buf
        if (q + 2 < NQ) {
            load_b_chunk(sb, jc0, q + 2, buf, tid);
            CP_ASYNC_COMMIT();
            CP_ASYNC_WAIT1();                 // chunk q+1 landed
        } else {
            CP_ASYNC_WAIT0();
        }
        __syncthreads();
    }

    // reduce across the 4 lanes sharing each row (lane bits 0-1)
    #pragma unroll
    for (int r = 0; r < 4; r++) {
        #pragma unroll
        for (int off = 1; off <= 2; off <<= 1) {
            minS[r] = fminf(minS[r], __shfl_xor_sync(0xffffffffu, minS[r], off));
            maxD[r] = fmaxf(maxD[r], __shfl_xor_sync(0xffffffffu, maxD[r], off));
        }
    }
    if ((lane & 3) == 0) {
        const int seg = (split * 2 + warp_n) * MAX_B;
        #pragma unroll
        for (int r = 0; r < 4; r++) {
            g_pmin[seg + rows[r]] = minS[r];
            g_pmax[seg + rows[r]] = maxD[r];
        }
    }
}

// ---------------------------------------------------------------------------
// Kernel 4: final reduction over segments + scalar loss.
// ---------------------------------------------------------------------------
__global__ void finalize_kernel(float* __restrict__ out, int B) {
    __shared__ float ssum[32];
    __shared__ int   scnt[32];
    float sum = 0.f;
    int   cnt = 0;
    for (int i = threadIdx.x; i < B; i += blockDim.x) {
        float mn = 1e38f, mx = -1e38f;
        #pragma unroll
        for (int s = 0; s < NSPLIT_EFF; s++) {
            mn = fminf(mn, g_pmin[s * MAX_B + i]);
            mx = fmaxf(mx, g_pmax[s * MAX_B + i]);
        }
        if (mn < 1e37f && mx > -1e37f) {
            float t = mx - mn + MARGIN;
            sum += (t > 0.f) ? t : 0.f;
            cnt += 1;
        }
    }
    #pragma unroll
    for (int off = 16; off > 0; off >>= 1) {
        sum += __shfl_xor_sync(0xffffffffu, sum, off);
        cnt += __shfl_xor_sync(0xffffffffu, cnt, off);
    }
    int lane = threadIdx.x & 31;
    int wid = threadIdx.x >> 5;
    if (lane == 0) { ssum[wid] = sum; scnt[wid] = cnt; }
    __syncthreads();
    if (wid == 0) {
        int nw = (blockDim.x + 31) >> 5;
        sum = (lane < nw) ? ssum[lane] : 0.f;
        cnt = (lane < nw) ? scnt[lane] : 0;
        #pragma unroll
        for (int off = 16; off > 0; off >>= 1) {
            sum += __shfl_xor_sync(0xffffffffu, sum, off);
            cnt += __shfl_xor_sync(0xffffffffu, cnt, off);
        }
        if (lane == 0) {
            int denom = cnt > 1 ? cnt : 1;
            out[0] = sum / (float)denom;
        }
    }
}

// ---------------------------------------------------------------------------
extern "C" void kernel_launch(void* const* d_in, const int* in_sizes, int n_in,
                              void* d_out, int out_size) {
    const float* emb = (const float*)d_in[0];
    const int*   lab = (const int*)d_in[1];
    int B = in_sizes[1];
    int D = in_sizes[0] / B;

    cudaFuncSetAttribute(sim_mma_kernel,
                         cudaFuncAttributeMaxDynamicSharedMemorySize, SM_TOTAL);

    norm_split_kernel<<<(B + 7) / 8, 256>>>(emb, B, D);
    fam_kernel<<<1, 1024>>>(lab, B);
    dim3 grid(B / BMC, NSPLIT);
    sim_mma_kernel<<<grid, 256, SM_TOTAL>>>();
    finalize_kernel<<<1, 1024>>>((float*)d_out, B);
}

// round 7
// speedup vs baseline: 1.0068x; 1.0068x over previous
#include <cuda_runtime.h>
#include <cuda_bf16.h>
#include <math.h>
#include <stdint.h>

// ---------------------------------------------------------------------------
// HierarchicalAffinityLoss via bf16-split (hi/lo) mma.sync GEMM, round 5.
// 128x128 CTA tile, 32x64 warp tile: halves per-output SMEM/ldmatrix traffic
// (R4 was crossbar-bound at 490 MAC/cyc/SM). XOR-swizzled 512B rows, A panel
// resident in SMEM, B streamed in k64 chunks (2-stage cp.async pipeline).
// B = 8192, D = 256.
// ---------------------------------------------------------------------------

#define MAX_B 8192
#define MAX_D 256
#define MARGIN 0.3f

#define BMC 128                      // CTA rows
#define BNC 128                      // CTA tile cols
#define NSPLIT 8                     // column splits (grid.y)
#define NSPLIT_EFF 16                // NSPLIT * 2 warp_n groups
#define COLSPAN (MAX_B / NSPLIT)     // 1024
#define NT (COLSPAN / BNC)           // 8 tiles per CTA
#define NQ (NT * 4)                  // 32 k64-chunks per CTA

// SMEM layout (512B rows, XOR swizzle chunk^(row&7); no padding)
#define A_HI   0                     // 128 rows x 512B = 64KB
#define A_LO   65536                 // 64KB
#define B_BUF  131072                // 2 stages x 32KB
#define B_STAGE 32768
#define B_LOO  16384                 // lo half within a stage
#define SFAM   196608                // 1024 ints = 4KB
#define SM_TOTAL 200704

__device__ __nv_bfloat16 g_hi[MAX_B * MAX_D];
__device__ __nv_bfloat16 g_lo[MAX_B * MAX_D];
__device__ int   g_fam[MAX_B];
__device__ float g_pmin[NSPLIT_EFF * MAX_B];
__device__ float g_pmax[NSPLIT_EFF * MAX_B];

__device__ __constant__ int c_fam_table[6] = {0, 1, 2, 1, 3, 3};

// ======================= PTX helpers =======================================
__device__ __forceinline__ uint32_t smem_u32(const void* p) {
    uint32_t a;
    asm("{ .reg .u64 t; cvta.to.shared.u64 t, %1; cvt.u32.u64 %0, t; }"
        : "=r"(a) : "l"(p));
    return a;
}
#define CP_ASYNC16(saddr, gaddr) \
    asm volatile("cp.async.cg.shared.global [%0], [%1], 16;" :: "r"(saddr), "l"(gaddr))
#define CP_ASYNC_COMMIT() asm volatile("cp.async.commit_group;" ::: "memory")
#define CP_ASYNC_WAIT0()  asm volatile("cp.async.wait_group 0;" ::: "memory")
#define CP_ASYNC_WAIT1()  asm volatile("cp.async.wait_group 1;" ::: "memory")

#define LDSM_X4(r, addr)                                                    \
    asm volatile("ldmatrix.sync.aligned.m8n8.x4.shared.b16 {%0,%1,%2,%3}, [%4];" \
        : "=r"((r)[0]), "=r"((r)[1]), "=r"((r)[2]), "=r"((r)[3]) : "r"(addr))
#define MMA16816(d, a, b0, b1)                                              \
    asm volatile("mma.sync.aligned.m16n8k16.row.col.f32.bf16.bf16.f32 "     \
        "{%0,%1,%2,%3},{%4,%5,%6,%7},{%8,%9},{%0,%1,%2,%3};"                \
        : "+f"((d)[0]), "+f"((d)[1]), "+f"((d)[2]), "+f"((d)[3])            \
        : "r"((a)[0]), "r"((a)[1]), "r"((a)[2]), "r"((a)[3]),               \
          "r"(b0), "r"(b1))

// ---------------------------------------------------------------------------
// Kernel 1: row L2-normalize + split into bf16 hi/lo. One warp per row.
// ---------------------------------------------------------------------------
__global__ __launch_bounds__(256) void norm_split_kernel(const float* __restrict__ emb,
                                                         int B, int D) {
    int row = blockIdx.x * (blockDim.x >> 5) + (threadIdx.x >> 5);
    if (row >= B) return;
    int lane = threadIdx.x & 31;
    const float* src = emb + (size_t)row * D;
    float s = 0.f;
    for (int k = lane; k < D; k += 32) {
        float v = src[k];
        s = fmaf(v, v, s);
    }
    #pragma unroll
    for (int off = 16; off > 0; off >>= 1)
        s += __shfl_xor_sync(0xffffffffu, s, off);
    float inv = 1.0f / sqrtf(s);
    for (int k = lane; k < D; k += 32) {
        float v = src[k] * inv;
        __nv_bfloat16 h = __float2bfloat16(v);
        float lo = v - __bfloat162float(h);
        g_hi[(size_t)row * D + k] = h;
        g_lo[(size_t)row * D + k] = __float2bfloat16(lo);
    }
}

// ---------------------------------------------------------------------------
// Kernel 2: family lookup with int64/int32 auto-detect (proven in R2/R4).
// ---------------------------------------------------------------------------
__global__ void fam_kernel(const int* __restrict__ lab32, int B) {
    int t = threadIdx.x;
    int bad = 0;
    if (t < 64) {
        int lo = lab32[2 * t];
        int hi = lab32[2 * t + 1];
        if (hi != 0 || lo < 0 || lo >= 64) bad = 1;
    }
    int any_bad = __syncthreads_or(bad);
    bool as64 = (any_bad == 0);
    for (int i = t; i < B; i += blockDim.x) {
        long long l;
        if (as64) l = ((const long long*)lab32)[i];
        else      l = (long long)lab32[i];
        int fam;
        if (l < 6) {
            int idx = (int)l;
            if (idx < 0) idx = 0;
            if (idx > 5) idx = 5;
            fam = c_fam_table[idx];
        } else {
            fam = -1;
        }
        g_fam[i] = fam;
    }
}

// ---------------------------------------------------------------------------
// B k64-chunk loader: 128 cols x 64 k (hi+lo) = 32KB into one stage.
// Col j row = 128B = 8 x 16B chunks, swizzle c^(j&7).
// ---------------------------------------------------------------------------
__device__ __forceinline__ void load_b_chunk(uint32_t sb, int jc0, int q,
                                             int buf, int tid) {
    const int j0 = jc0 + (q >> 2) * BNC;
    const int kb = (q & 3) * 64;
    const uint32_t dst = sb + B_BUF + buf * B_STAGE;
    const char* ghi = (const char*)g_hi;
    const char* glo = (const char*)g_lo;
    #pragma unroll
    for (int it = 0; it < 4; it++) {
        int idx = it * 256 + tid;             // 0..1023
        int j = idx >> 3, c = idx & 7;
        uint32_t soff = (uint32_t)(j * 128 + ((c ^ (j & 7)) << 4));
        size_t goff = ((size_t)(j0 + j) * MAX_D + kb + c * 8) * 2;
        CP_ASYNC16(dst + soff, ghi + goff);
        CP_ASYNC16(dst + B_LOO + soff, glo + goff);
    }
}

// ---------------------------------------------------------------------------
// Kernel 3: bf16-split mma.sync Gram + fused masked min/max.
// ---------------------------------------------------------------------------
__global__ __launch_bounds__(256, 1) void sim_mma_kernel() {
    extern __shared__ char smem[];
    const uint32_t sb = smem_u32(smem);
    const int tid = threadIdx.x;
    const int wid = tid >> 5;
    const int lane = tid & 31;
    const int i0 = blockIdx.x * BMC;
    const int split = blockIdx.y;
    const int jc0 = split * COLSPAN;

    const int warp_m = wid & 3;          // 4 row-warps, 32 rows each
    const int warp_n = wid >> 2;         // 2 col-warps, 64 cols each
    const int m0 = warp_m * 32;

    // ---- prologue: resident A panel (hi+lo, swizzled 512B rows) ----
    {
        const char* ghi = (const char*)g_hi;
        const char* glo = (const char*)g_lo;
        #pragma unroll
        for (int it = 0; it < 16; it++) {
            int idx = it * 256 + tid;        // 0..4095
            int r = idx >> 5, c = idx & 31;
            uint32_t soff = (uint32_t)(r * 512 + ((c ^ (r & 7)) << 4));
            size_t goff = ((size_t)(i0 + r) * MAX_D + c * 8) * 2;
            CP_ASYNC16(sb + A_HI + soff, ghi + goff);
            CP_ASYNC16(sb + A_LO + soff, glo + goff);
        }
    }
    load_b_chunk(sb, jc0, 0, 0, tid);
    CP_ASYNC_COMMIT();                       // group0: A + chunk0
    load_b_chunk(sb, jc0, 1, 1, tid);
    CP_ASYNC_COMMIT();                       // group1: chunk1

    // fam cache for this CTA's column span
    int* sfam = (int*)(smem + SFAM);
    for (int c = tid; c < COLSPAN; c += 256)
        sfam[c] = g_fam[jc0 + c];

    // per-thread row state: 4 rows (2 m16-frags x 2 row-groups)
    const int g8 = lane >> 2;
    int rows[4], fam_i[4];
    float minS[4], maxD[4];
    #pragma unroll
    for (int r = 0; r < 4; r++) {
        rows[r] = i0 + m0 + r * 8 + g8;
        fam_i[r] = g_fam[rows[r]];
        minS[r] = 1e38f; maxD[r] = -1e38f;
    }

    // ldmatrix lane bases
    // A x4 serves rows ra..ra+15: lanes 0-7 row ra+l (k c), 8-15 row ra+8+l (k c),
    // 16-23 row ra+l (k c+1), 24-31 row ra+8+l (k c+1).
    const int arow = m0 + (lane & 7) + ((lane >> 3) & 1) * 8;  // first 16 rows
    const int sA = arow & 7;                                    // same for +16
    const uint32_t aHi0 = sb + A_HI + (uint32_t)(arow * 512);
    const uint32_t aHi1 = aHi0 + 16 * 512;
    const uint32_t aLo0 = sb + A_LO + (uint32_t)(arow * 512);
    const uint32_t aLo1 = aLo0 + 16 * 512;
    const int cLaneA = (lane >> 4);          // +1 chunk for upper half-warp

    // B x4 serves cols jb..jb+15 per np
    const int jbl = (lane & 7) + ((lane >> 3) & 1) * 8;

    CP_ASYNC_WAIT1();                        // A + chunk0 ready
    __syncthreads();

    float acc[2][8][4];
    #pragma unroll
    for (int mf = 0; mf < 2; mf++)
        #pragma unroll
        for (int nf = 0; nf < 8; nf++)
            #pragma unroll
            for (int c = 0; c < 4; c++) acc[mf][nf][c] = 0.f;

    for (int q = 0; q < NQ; q++) {
        const int buf = q & 1;
        const int kq = q & 3;
        const uint32_t bufb = sb + B_BUF + buf * B_STAGE;

        #pragma unroll
        for (int kk = 0; kk < 4; kk++) {
            const int cA = kq * 8 + 2 * kk + cLaneA;      // A chunk idx 0..31
            const uint32_t aoff = (uint32_t)((cA ^ sA) << 4);
            uint32_t ah0[4], ah1[4], al0[4], al1[4];
            LDSM_X4(ah0, aHi0 + aoff);
            LDSM_X4(ah1, aHi1 + aoff);
            LDSM_X4(al0, aLo0 + aoff);
            LDSM_X4(al1, aLo1 + aoff);

            #pragma unroll
            for (int np = 0; np < 4; np++) {
                const int j = warp_n * 64 + np * 16 + jbl;
                const int cB = 2 * kk + cLaneA;           // B chunk idx 0..7
                const uint32_t boff = (uint32_t)(j * 128 + ((cB ^ (j & 7)) << 4));
                uint32_t bh[4], bl[4];
                LDSM_X4(bh, bufb + boff);
                LDSM_X4(bl, bufb + B_LOO + boff);
                // frags: even n-tile = {r0,r2}, odd n-tile = {r1,r3}
                MMA16816(acc[0][2*np],   ah0, bh[0], bh[2]);
                MMA16816(acc[0][2*np+1], ah0, bh[1], bh[3]);
                MMA16816(acc[1][2*np],   ah1, bh[0], bh[2]);
                MMA16816(acc[1][2*np+1], ah1, bh[1], bh[3]);
                MMA16816(acc[0][2*np],   al0, bh[0], bh[2]);
                MMA16816(acc[0][2*np+1], al0, bh[1], bh[3]);
                MMA16816(acc[1][2*np],   al1, bh[0], bh[2]);
                MMA16816(acc[1][2*np+1], al1, bh[1], bh[3]);
                MMA16816(acc[0][2*np],   ah0, bl[0], bl[2]);
                MMA16816(acc[0][2*np+1], ah0, bl[1], bl[3]);
                MMA16816(acc[1][2*np],   ah1, bl[0], bl[2]);
                MMA16816(acc[1][2*np+1], ah1, bl[1], bl[3]);
            }
        }

        // tile complete -> masked min/max epilogue, reset acc
        if (kq == 3) {
            const int tjl = (q >> 2) * BNC + warp_n * 64;   // tile col base, local
            #pragma unroll
            for (int nf = 0; nf < 8; nf++) {
                const int jl = tjl + nf * 8 + (lane & 3) * 2;
                const int j0 = jc0 + jl;
                const int fj0 = sfam[jl];
                const int fj1 = sfam[jl + 1];
                #pragma unroll
                for (int mf = 0; mf < 2; mf++) {
                    #pragma unroll
                    for (int h = 0; h < 2; h++) {         // row-group within frag
                        const int ri = mf * 2 + h;
                        if (fam_i[ri] < 0) continue;
                        const float v0 = acc[mf][nf][h * 2];
                        const float v1 = acc[mf][nf][h * 2 + 1];
                        if (fj0 == fam_i[ri]) { if (j0 != rows[ri]) minS[ri] = fminf(minS[ri], v0); }
                        else if (fj0 >= 0) maxD[ri] = fmaxf(maxD[ri], v0);
                        if (fj1 == fam_i[ri]) { if (j0 + 1 != rows[ri]) minS[ri] = fminf(minS[ri], v1); }
                        else if (fj1 >= 0) maxD[ri] = fmaxf(maxD[ri], v1);
                    }
                }
            }
            #pragma unroll
            for (int mf = 0; mf < 2; mf++)
                #pragma unroll
                for (int nf = 0; nf < 8; nf++)
                    #pragma unroll
                    for (int c = 0; c < 4; c++) acc[mf][nf][c] = 0.f;
        }

        __syncthreads();                      // all warps done with buf
        if (q + 2 < NQ) {
            load_b_chunk(sb, jc0, q + 2, buf, tid);
            CP_ASYNC_COMMIT();
            CP_ASYNC_WAIT1();                 // chunk q+1 landed
        } else {
            CP_ASYNC_WAIT0();
        }
        __syncthreads();
    }

    // reduce across the 4 lanes sharing each row (lane bits 0-1)
    #pragma unroll
    for (int r = 0; r < 4; r++) {
        #pragma unroll
        for (int off = 1; off <= 2; off <<= 1) {
            minS[r] = fminf(minS[r], __shfl_xor_sync(0xffffffffu, minS[r], off));
            maxD[r] = fmaxf(maxD[r], __shfl_xor_sync(0xffffffffu, maxD[r], off));
        }
    }
    if ((lane & 3) == 0) {
        const int seg = (split * 2 + warp_n) * MAX_B;
        #pragma unroll
        for (int r = 0; r < 4; r++) {
            g_pmin[seg + rows[r]] = minS[r];
            g_pmax[seg + rows[r]] = maxD[r];
        }
    }
}

// ---------------------------------------------------------------------------
// Kernel 4: final reduction over segments + scalar loss.
// ---------------------------------------------------------------------------
__global__ void finalize_kernel(float* __restrict__ out, int B) {
    __shared__ float ssum[32];
    __shared__ int   scnt[32];
    float sum = 0.f;
    int   cnt = 0;
    for (int i = threadIdx.x; i < B; i += blockDim.x) {
        float mn = 1e38f, mx = -1e38f;
        #pragma unroll
        for (int s = 0; s < NSPLIT_EFF; s++) {
            mn = fminf(mn, g_pmin[s * MAX_B + i]);
            mx = fmaxf(mx, g_pmax[s * MAX_B + i]);
        }
        if (mn < 1e37f && mx > -1e37f) {
            float t = mx - mn + MARGIN;
            sum += (t > 0.f) ? t : 0.f;
            cnt += 1;
        }
    }
    #pragma unroll
    for (int off = 16; off > 0; off >>= 1) {
        sum += __shfl_xor_sync(0xffffffffu, sum, off);
        cnt += __shfl_xor_sync(0xffffffffu, cnt, off);
    }
    int lane = threadIdx.x & 31;
    int wid = threadIdx.x >> 5;
    if (lane == 0) { ssum[wid] = sum; scnt[wid] = cnt; }
    __syncthreads();
    if (wid == 0) {
        int nw = (blockDim.x + 31) >> 5;
        sum = (lane < nw) ? ssum[lane] : 0.f;
        cnt = (lane < nw) ? scnt[lane] : 0;
        #pragma unroll
        for (int off = 16; off > 0; off >>= 1) {
            sum += __shfl_xor_sync(0xffffffffu, sum, off);
            cnt += __shfl_xor_sync(0xffffffffu, cnt, off);
        }
        if (lane == 0) {
            int denom = cnt > 1 ? cnt : 1;
            out[0] = sum / (float)denom;
        }
    }
}

// ---------------------------------------------------------------------------
extern "C" void kernel_launch(void* const* d_in, const int* in_sizes, int n_in,
                              void* d_out, int out_size) {
    const float* emb = (const float*)d_in[0];
    const int*   lab = (const int*)d_in[1];
    int B = in_sizes[1];
    int D = in_sizes[0] / B;

    cudaFuncSetAttribute(sim_mma_kernel,
                         cudaFuncAttributeMaxDynamicSharedMemorySize, SM_TOTAL);

    norm_split_kernel<<<(B + 7) / 8, 256>>>(emb, B, D);
    fam_kernel<<<1, 1024>>>(lab, B);
    dim3 grid(B / BMC, NSPLIT);
    sim_mma_kernel<<<grid, 256, SM_TOTAL>>>();
    finalize_kernel<<<1, 1024>>>((float*)d_out, B);
}